// round 10
// baseline (speedup 1.0000x reference)
#include <cuda_runtime.h>
#include <math.h>

#define FULL 0xffffffffu
typedef unsigned long long u64;

// Scratch token buffer: (B=16, T=128, slots=67, EMBED=32) fp32
__device__ float g_tokens[16 * 128 * 67 * 32];

__device__ __forceinline__ float warp_sum(float v) {
    v += __shfl_xor_sync(FULL, v, 16);
    v += __shfl_xor_sync(FULL, v, 8);
    v += __shfl_xor_sync(FULL, v, 4);
    v += __shfl_xor_sync(FULL, v, 2);
    v += __shfl_xor_sync(FULL, v, 1);
    return v;
}

// ---- packed f32x2 helpers ----
__device__ __forceinline__ u64 fma2(u64 a, u64 b, u64 c) {
    u64 d; asm("fma.rn.f32x2 %0, %1, %2, %3;" : "=l"(d) : "l"(a), "l"(b), "l"(c)); return d;
}
__device__ __forceinline__ u64 mul2(u64 a, u64 b) {
    u64 d; asm("mul.rn.f32x2 %0, %1, %2;" : "=l"(d) : "l"(a), "l"(b)); return d;
}
__device__ __forceinline__ u64 add2(u64 a, u64 b) {
    u64 d; asm("add.rn.f32x2 %0, %1, %2;" : "=l"(d) : "l"(a), "l"(b)); return d;
}
__device__ __forceinline__ u64 pack2(float lo, float hi) {
    u64 d; asm("mov.b64 %0, {%1, %2};" : "=l"(d) : "f"(lo), "f"(hi)); return d;
}
__device__ __forceinline__ float hsum2(u64 v) {
    float lo, hi; asm("mov.b64 {%0, %1}, %2;" : "=f"(lo), "=f"(hi) : "l"(v)); return lo + hi;
}
__device__ __forceinline__ float ex2f(float x) {
    float y; asm("ex2.approx.f32 %0, %1;" : "=f"(y) : "f"(x)); return y;
}

__device__ __forceinline__ void ld_row16(u64* r, const float* p) {
    const ulonglong2* q = (const ulonglong2*)p;
#pragma unroll
    for (int i = 0; i < 8; i++) { ulonglong2 t = q[i]; r[2 * i] = t.x; r[2 * i + 1] = t.y; }
}

// one weight row read, TWO dots (token pair)
__device__ __forceinline__ float2 dot32x2(const float* wrow, const u64* a, const u64* b) {
    const ulonglong2* w = (const ulonglong2*)wrow;
    ulonglong2 t0 = w[0], t1 = w[1];
    u64 a0 = mul2(a[0], t0.x), b0 = mul2(b[0], t0.x);
    a0 = fma2(a[1], t0.y, a0); b0 = fma2(b[1], t0.y, b0);
    u64 a1 = mul2(a[2], t1.x), b1 = mul2(b[2], t1.x);
    a1 = fma2(a[3], t1.y, a1); b1 = fma2(b[3], t1.y, b1);
#pragma unroll
    for (int i = 2; i < 8; i += 2) {
        ulonglong2 u0 = w[i], u1 = w[i + 1];
        a0 = fma2(a[2 * i], u0.x, a0);     b0 = fma2(b[2 * i], u0.x, b0);
        a0 = fma2(a[2 * i + 1], u0.y, a0); b0 = fma2(b[2 * i + 1], u0.y, b0);
        a1 = fma2(a[2 * i + 2], u1.x, a1); b1 = fma2(b[2 * i + 2], u1.x, b1);
        a1 = fma2(a[2 * i + 3], u1.y, a1); b1 = fma2(b[2 * i + 3], u1.y, b1);
    }
    return make_float2(hsum2(add2(a0, a1)), hsum2(add2(b0, b1)));
}

__device__ __forceinline__ float sumsq16(const u64* v) {
    u64 a0 = mul2(v[0], v[0]);
    u64 a1 = mul2(v[1], v[1]);
#pragma unroll
    for (int i = 2; i < 16; i += 2) {
        a0 = fma2(v[i], v[i], a0);
        a1 = fma2(v[i + 1], v[i + 1], a1);
    }
    return hsum2(add2(a0, a1));
}

// ---------------------------------------------------------------------------
// Kernel 0: tokenize + input rmsnorm. grid = B*T (2048), block = 256.
// ---------------------------------------------------------------------------
__global__ void embed_kernel(const float* __restrict__ obs,
                             const float* __restrict__ Wval,
                             const float* __restrict__ bval,
                             const float* __restrict__ innorm,
                             const float* __restrict__ dimemb,
                             const float* __restrict__ cls) {
    int bt = blockIdx.x;
    int tid = threadIdx.x;
    int wid = tid >> 5, lane = tid & 31;
    for (int s = wid; s < 67; s += 8) {
        float val;
        if (s < 64)
            val = fmaf(obs[bt * 64 + s], Wval[lane], bval[lane]) + dimemb[s * 32 + lane];
        else
            val = cls[(s - 64) * 32 + lane];
        float ms = warp_sum(val * val) * (1.f / 32.f);
        g_tokens[(bt * 67 + s) * 32 + lane] = val * rsqrtf(ms + 1e-6f) * innorm[lane];
    }
}

// ---------------------------------------------------------------------------
// Kernel A: attention half of the block.
// rmsnorm -> QKV (+qk-norm, rope) -> attention -> Wo -> rmsnorm residual.
// Writes xn back to g_tokens. Two tokens per lane, head-split attention.
// Spatial variant runs at 3 CTAs/SM (12 warps).
// ---------------------------------------------------------------------------
template <int S, int NSEQ, int MINB, bool TEMPORAL>
__global__ void __launch_bounds__(128, MINB)
attn_half(const float* __restrict__ Wq, const float* __restrict__ Wk,
          const float* __restrict__ Wv, const float* __restrict__ Wo,
          const float* __restrict__ norm4, const float* __restrict__ qkn,
          int nseq_total) {
    constexpr int HS = (S + 1) / 2;
    constexpr int ROW = 36;
    // de-alias sequence bases if stride is a multiple of 32 banks
    constexpr int SEQSTR = 2 * S * ROW + (((2 * S * ROW) & 31) == 0 ? 8 : 0);
    constexpr int DATSZ = NSEQ * SEQSTR;

    extern __shared__ float sm[];
    float* skv   = sm;                 // DATSZ
    float* swq   = skv + DATSZ;        // 1024
    float* swk   = swq + 1024;
    float* swv   = swk + 1024;
    float* swo   = swv + 1024;
    float* snorm = swo + 1024;         // 64 (norm rows 0,1)
    float* sqkn  = snorm + 64;         // 16

    const int tid = threadIdx.x;
    int gseq0 = blockIdx.x * NSEQ;

    for (int i = tid; i < 256; i += 128) {
        ((float4*)swq)[i] = ((const float4*)Wq)[i];
        ((float4*)swk)[i] = ((const float4*)Wk)[i];
        ((float4*)swv)[i] = ((const float4*)Wv)[i];
        ((float4*)swo)[i] = ((const float4*)Wo)[i];
    }
    if (tid < 64) snorm[tid] = norm4[tid];
    if (tid < 16) sqkn[tid] = qkn[tid];

    // token-pair assignment
    int seq = tid / HS;
    int l = tid - seq * HS;
    bool seqok = (seq < NSEQ) && (gseq0 + seq < nseq_total);
    int seqc = seqok ? seq : 0;
    bool vA = seqok;
    bool vB = seqok && (l + HS < S);
    int tokA = l;
    int tokB = vB ? (l + HS) : (S - 1);

    float* kb = skv + seqc * SEQSTR;
    float* vb = kb + S * ROW;

    float *gxA, *gxB;
    {
        int gs = gseq0 + seqc;
        if (TEMPORAL) {
            int b = gs / 67, sl = gs - b * 67;
            gxA = g_tokens + ((long)(b * 128 + tokA) * 67 + sl) * 32;
            gxB = g_tokens + ((long)(b * 128 + tokB) * 67 + sl) * 32;
        } else {
            gxA = g_tokens + ((long)gs * 67 + tokA) * 32;
            gxB = g_tokens + ((long)gs * 67 + tokB) * 32;
        }
    }

    __syncthreads();

    u64 qA[16], qB[16];

    // ================= Phase B: norm + QKV (+qk-norm, rope) ================
    if (vA) {
        float qknQ[8], qknK[8];
#pragma unroll
        for (int e = 0; e < 8; e++) {
            qknQ[e] = sqkn[e] * (0.35355339059327373f * 1.4426950408889634f);
            qknK[e] = sqkn[8 + e];
        }
        float csA[4], snA[4], csB[4], snB[4];
        if (TEMPORAL) {
            const float th[4] = {1.f, 0.1f, 0.01f, 0.001f};
#pragma unroll
            for (int j = 0; j < 4; j++) {
                __sincosf((float)tokA * th[j], &snA[j], &csA[j]);
                __sincosf((float)tokB * th[j], &snB[j], &csB[j]);
            }
        }

        u64 hA[16], hB[16];
        {
            u64 x2[16];
            ld_row16(x2, gxA);
            float rs = rsqrtf(sumsq16(x2) * 0.03125f + 1e-6f);
            u64 rs2 = pack2(rs, rs);
            const ulonglong2* nw = (const ulonglong2*)snorm;
#pragma unroll
            for (int i = 0; i < 8; i++) {
                ulonglong2 n = nw[i];
                hA[2 * i] = mul2(mul2(x2[2 * i], rs2), n.x);
                hA[2 * i + 1] = mul2(mul2(x2[2 * i + 1], rs2), n.y);
            }
            ld_row16(x2, gxB);
            rs = rsqrtf(sumsq16(x2) * 0.03125f + 1e-6f);
            rs2 = pack2(rs, rs);
#pragma unroll
            for (int i = 0; i < 8; i++) {
                ulonglong2 n = nw[i];
                hB[2 * i] = mul2(mul2(x2[2 * i], rs2), n.x);
                hB[2 * i + 1] = mul2(mul2(x2[2 * i + 1], rs2), n.y);
            }
        }

        // ---- K heads ----
#pragma unroll 1
        for (int hh = 0; hh < 4; hh++) {
            float aA[8], aB[8];
#pragma unroll
            for (int e = 0; e < 8; e++) {
                float2 d = dot32x2(swk + (hh * 8 + e) * 32, hA, hB);
                aA[e] = d.x; aB[e] = d.y;
            }
            float msA = 0, msB = 0;
#pragma unroll
            for (int e = 0; e < 8; e++) { msA = fmaf(aA[e], aA[e], msA); msB = fmaf(aB[e], aB[e], msB); }
            float scA = rsqrtf(msA * 0.125f + 1e-6f);
            float scB = rsqrtf(msB * 0.125f + 1e-6f);
#pragma unroll
            for (int e = 0; e < 8; e++) { aA[e] *= scA * qknK[e]; aB[e] *= scB * qknK[e]; }
            if (TEMPORAL) {
#pragma unroll
                for (int e = 0; e < 4; e++) {
                    float t0 = aA[e], t1 = aA[e + 4];
                    aA[e] = t0 * csA[e] - t1 * snA[e];
                    aA[e + 4] = fmaf(t0, snA[e], t1 * csA[e]);
                    t0 = aB[e]; t1 = aB[e + 4];
                    aB[e] = t0 * csB[e] - t1 * snB[e];
                    aB[e + 4] = fmaf(t0, snB[e], t1 * csB[e]);
                }
            }
            float* dA = kb + tokA * ROW + hh * 8;
            *(float4*)dA = make_float4(aA[0], aA[1], aA[2], aA[3]);
            *(float4*)(dA + 4) = make_float4(aA[4], aA[5], aA[6], aA[7]);
            if (vB) {
                float* dB = kb + tokB * ROW + hh * 8;
                *(float4*)dB = make_float4(aB[0], aB[1], aB[2], aB[3]);
                *(float4*)(dB + 4) = make_float4(aB[4], aB[5], aB[6], aB[7]);
            }
        }

        // ---- V heads ----
#pragma unroll 1
        for (int hh = 0; hh < 4; hh++) {
            float aA[8], aB[8];
#pragma unroll
            for (int e = 0; e < 8; e++) {
                float2 d = dot32x2(swv + (hh * 8 + e) * 32, hA, hB);
                aA[e] = d.x; aB[e] = d.y;
            }
            float* dA = vb + tokA * ROW + hh * 8;
            *(float4*)dA = make_float4(aA[0], aA[1], aA[2], aA[3]);
            *(float4*)(dA + 4) = make_float4(aA[4], aA[5], aA[6], aA[7]);
            if (vB) {
                float* dB = vb + tokB * ROW + hh * 8;
                *(float4*)dB = make_float4(aB[0], aB[1], aB[2], aB[3]);
                *(float4*)(dB + 4) = make_float4(aB[4], aB[5], aB[6], aB[7]);
            }
        }

        // ---- Q heads ----
#pragma unroll
        for (int hh = 0; hh < 4; hh++) {
            float aA[8], aB[8];
#pragma unroll
            for (int e = 0; e < 8; e++) {
                float2 d = dot32x2(swq + (hh * 8 + e) * 32, hA, hB);
                aA[e] = d.x; aB[e] = d.y;
            }
            float msA = 0, msB = 0;
#pragma unroll
            for (int e = 0; e < 8; e++) { msA = fmaf(aA[e], aA[e], msA); msB = fmaf(aB[e], aB[e], msB); }
            float scA = rsqrtf(msA * 0.125f + 1e-6f);
            float scB = rsqrtf(msB * 0.125f + 1e-6f);
#pragma unroll
            for (int e = 0; e < 8; e++) { aA[e] *= scA * qknQ[e]; aB[e] *= scB * qknQ[e]; }
            if (TEMPORAL) {
#pragma unroll
                for (int e = 0; e < 4; e++) {
                    float t0 = aA[e], t1 = aA[e + 4];
                    aA[e] = t0 * csA[e] - t1 * snA[e];
                    aA[e + 4] = fmaf(t0, snA[e], t1 * csA[e]);
                    t0 = aB[e]; t1 = aB[e + 4];
                    aB[e] = t0 * csB[e] - t1 * snB[e];
                    aB[e + 4] = fmaf(t0, snB[e], t1 * csB[e]);
                }
            }
#pragma unroll
            for (int j = 0; j < 4; j++) {
                qA[4 * hh + j] = pack2(aA[2 * j], aA[2 * j + 1]);
                qB[4 * hh + j] = pack2(aB[2 * j], aB[2 * j + 1]);
            }
        }
    }
    __syncthreads();

    // ====== Phase C: attention, two head-split passes =======
    u64 oA[16], oB[16];
    if (vA) {
#pragma unroll
        for (int pass = 0; pass < 2; pass++) {
            u64 aA[8], aB[8];
#pragma unroll
            for (int i = 0; i < 8; i++) { aA[i] = 0ULL; aB[i] = 0ULL; }
            float l0A = 0.f, l1A = 0.f, l0B = 0.f, l1B = 0.f;
            const float* kp = kb + 16 * pass;
            const float* vp = vb + 16 * pass;
            const u64* qAp = qA + 8 * pass;
            const u64* qBp = qB + 8 * pass;

#pragma unroll 2
            for (int j = 0; j < S; j++) {
                const ulonglong2* kr = (const ulonglong2*)(kp + j * ROW);
                ulonglong2 k0 = kr[0], k1 = kr[1], k2 = kr[2], k3 = kr[3];
                u64 cA0 = fma2(qAp[1], k0.y, mul2(qAp[0], k0.x));
                u64 dA0 = fma2(qAp[3], k1.y, mul2(qAp[2], k1.x));
                u64 cA1 = fma2(qAp[5], k2.y, mul2(qAp[4], k2.x));
                u64 dA1 = fma2(qAp[7], k3.y, mul2(qAp[6], k3.x));
                u64 cB0 = fma2(qBp[1], k0.y, mul2(qBp[0], k0.x));
                u64 dB0 = fma2(qBp[3], k1.y, mul2(qBp[2], k1.x));
                u64 cB1 = fma2(qBp[5], k2.y, mul2(qBp[4], k2.x));
                u64 dB1 = fma2(qBp[7], k3.y, mul2(qBp[6], k3.x));
                float pA0 = ex2f(hsum2(add2(cA0, dA0)));
                float pA1 = ex2f(hsum2(add2(cA1, dA1)));
                float pB0 = ex2f(hsum2(add2(cB0, dB0)));
                float pB1 = ex2f(hsum2(add2(cB1, dB1)));
                l0A += pA0; l1A += pA1; l0B += pB0; l1B += pB1;

                const ulonglong2* vr = (const ulonglong2*)(vp + j * ROW);
                ulonglong2 v0 = vr[0], v1 = vr[1], v2 = vr[2], v3 = vr[3];
                u64 pp;
                pp = pack2(pA0, pA0);
                aA[0] = fma2(pp, v0.x, aA[0]); aA[1] = fma2(pp, v0.y, aA[1]);
                aA[2] = fma2(pp, v1.x, aA[2]); aA[3] = fma2(pp, v1.y, aA[3]);
                pp = pack2(pA1, pA1);
                aA[4] = fma2(pp, v2.x, aA[4]); aA[5] = fma2(pp, v2.y, aA[5]);
                aA[6] = fma2(pp, v3.x, aA[6]); aA[7] = fma2(pp, v3.y, aA[7]);
                pp = pack2(pB0, pB0);
                aB[0] = fma2(pp, v0.x, aB[0]); aB[1] = fma2(pp, v0.y, aB[1]);
                aB[2] = fma2(pp, v1.x, aB[2]); aB[3] = fma2(pp, v1.y, aB[3]);
                pp = pack2(pB1, pB1);
                aB[4] = fma2(pp, v2.x, aB[4]); aB[5] = fma2(pp, v2.y, aB[5]);
                aB[6] = fma2(pp, v3.x, aB[6]); aB[7] = fma2(pp, v3.y, aB[7]);
            }
            float i0A = __fdividef(1.f, l0A), i1A = __fdividef(1.f, l1A);
            float i0B = __fdividef(1.f, l0B), i1B = __fdividef(1.f, l1B);
            u64 z;
            z = pack2(i0A, i0A);
#pragma unroll
            for (int i = 0; i < 4; i++) oA[8 * pass + i] = mul2(aA[i], z);
            z = pack2(i1A, i1A);
#pragma unroll
            for (int i = 4; i < 8; i++) oA[8 * pass + i] = mul2(aA[i], z);
            z = pack2(i0B, i0B);
#pragma unroll
            for (int i = 0; i < 4; i++) oB[8 * pass + i] = mul2(aB[i], z);
            z = pack2(i1B, i1B);
#pragma unroll
            for (int i = 4; i < 8; i++) oB[8 * pass + i] = mul2(aB[i], z);
        }
    }

    // ================= Phase D: Wo + rmsnorm residual -> gmem ==============
    if (vA) {
        float owA[32], owB[32];
        float ssA = 0.f, ssB = 0.f;
#pragma unroll
        for (int d = 0; d < 32; d++) {
            float2 r = dot32x2(swo + d * 32, oA, oB);
            owA[d] = r.x; owB[d] = r.y;
            ssA = fmaf(r.x, r.x, ssA);
            ssB = fmaf(r.y, r.y, ssB);
        }
        float rA = rsqrtf(ssA * 0.03125f + 1e-6f);
        float rB = rsqrtf(ssB * 0.03125f + 1e-6f);
        u64 rsA = pack2(rA, rA);
        u64 rsB = pack2(rB, rB);
        const ulonglong2* nw1 = (const ulonglong2*)(snorm + 32);

        {
            u64 x2[16];
            ld_row16(x2, gxA);
            ulonglong2* go = (ulonglong2*)gxA;
#pragma unroll
            for (int i = 0; i < 8; i++) {
                ulonglong2 n = nw1[i];
                ulonglong2 r;
                r.x = fma2(mul2(pack2(owA[4 * i], owA[4 * i + 1]), rsA), n.x, x2[2 * i]);
                r.y = fma2(mul2(pack2(owA[4 * i + 2], owA[4 * i + 3]), rsA), n.y, x2[2 * i + 1]);
                go[i] = r;
            }
        }
        if (vB) {
            u64 x2[16];
            ld_row16(x2, gxB);
            ulonglong2* go = (ulonglong2*)gxB;
#pragma unroll
            for (int i = 0; i < 8; i++) {
                ulonglong2 n = nw1[i];
                ulonglong2 r;
                r.x = fma2(mul2(pack2(owB[4 * i], owB[4 * i + 1]), rsB), n.x, x2[2 * i]);
                r.y = fma2(mul2(pack2(owB[4 * i + 2], owB[4 * i + 3]), rsB), n.y, x2[2 * i + 1]);
                go[i] = r;
            }
        }
    }
}

// ---------------------------------------------------------------------------
// Kernel B: FFN half. 256 tokens per CTA (flat token order), pair per lane,
// xn staged coalesced through smem, 3 CTAs/SM.
// ---------------------------------------------------------------------------
__global__ void __launch_bounds__(128, 3)
ffn_half(const float* __restrict__ Wg, const float* __restrict__ Wu,
         const float* __restrict__ Wout, const float* __restrict__ normF) {
    extern __shared__ float sm[];
    float* sx    = sm;                // 256*36 = 9216
    float* swg   = sx + 9216;         // 2048
    float* swu   = swg + 2048;        // 2048
    float* swout = swu + 2048;        // 2048 transposed [f][d]
    float* snF   = swout + 2048;      // 64 (norm rows 2,3)

    const int tid = threadIdx.x;
    long base = (long)blockIdx.x * 8192;

    for (int i = tid; i < 512; i += 128) {
        ((float4*)swg)[i] = ((const float4*)Wg)[i];
        ((float4*)swu)[i] = ((const float4*)Wu)[i];
    }
    for (int i = tid; i < 2048; i += 128) {
        int f = i >> 5, d = i & 31;
        swout[i] = Wout[d * 64 + f];
    }
    if (tid < 64) snF[tid] = normF[tid];
    // coalesced stage of 256 token rows
    for (int i = tid; i < 2048; i += 128)
        *(float4*)(sx + (i >> 3) * 36 + (i & 7) * 4) = ((const float4*)(g_tokens + base))[i];
    __syncthreads();

    // rows tid and tid+128
    u64 h2A[16], h2B[16];
    {
        u64 xn[16];
        ld_row16(xn, sx + tid * 36);
        float rs = rsqrtf(sumsq16(xn) * 0.03125f + 1e-6f);
        u64 rs2 = pack2(rs, rs);
        const ulonglong2* nw = (const ulonglong2*)snF;
#pragma unroll
        for (int i = 0; i < 8; i++) {
            ulonglong2 n = nw[i];
            h2A[2 * i] = mul2(mul2(xn[2 * i], rs2), n.x);
            h2A[2 * i + 1] = mul2(mul2(xn[2 * i + 1], rs2), n.y);
        }
        ld_row16(xn, sx + (tid + 128) * 36);
        rs = rsqrtf(sumsq16(xn) * 0.03125f + 1e-6f);
        rs2 = pack2(rs, rs);
#pragma unroll
        for (int i = 0; i < 8; i++) {
            ulonglong2 n = nw[i];
            h2B[2 * i] = mul2(mul2(xn[2 * i], rs2), n.x);
            h2B[2 * i + 1] = mul2(mul2(xn[2 * i + 1], rs2), n.y);
        }
    }

    u64 ovA[16], ovB[16];
#pragma unroll
    for (int i = 0; i < 16; i++) { ovA[i] = 0ULL; ovB[i] = 0ULL; }

#pragma unroll 1
    for (int fg = 0; fg < 16; fg++) {
#pragma unroll
        for (int e = 0; e < 4; e++) {
            int f = fg * 4 + e;
            float2 g2 = dot32x2(swg + f * 32, h2A, h2B);
            float2 u2 = dot32x2(swu + f * 32, h2A, h2B);
            float fvA = __fdividef(g2.x, 1.f + __expf(-g2.x)) * u2.x;
            float fvB = __fdividef(g2.y, 1.f + __expf(-g2.y)) * u2.y;
            u64 fA = pack2(fvA, fvA), fB = pack2(fvB, fvB);
            const ulonglong2* wr = (const ulonglong2*)(swout + f * 32);
#pragma unroll
            for (int i = 0; i < 8; i++) {
                ulonglong2 t = wr[i];
                ovA[2 * i] = fma2(fA, t.x, ovA[2 * i]);
                ovA[2 * i + 1] = fma2(fA, t.y, ovA[2 * i + 1]);
                ovB[2 * i] = fma2(fB, t.x, ovB[2 * i]);
                ovB[2 * i + 1] = fma2(fB, t.y, ovB[2 * i + 1]);
            }
        }
    }

    // out = xn + rmsnorm(ov)*norm3; write into own sx row, then sweep out
    {
        const ulonglong2* nw = (const ulonglong2*)(snF + 32);
        float rs3 = rsqrtf(sumsq16(ovA) * 0.03125f + 1e-6f);
        u64 rs32 = pack2(rs3, rs3);
        u64 xn[16];
        ld_row16(xn, sx + tid * 36);
        ulonglong2* xo = (ulonglong2*)(sx + tid * 36);
#pragma unroll
        for (int i = 0; i < 8; i++) {
            ulonglong2 n = nw[i];
            ulonglong2 r;
            r.x = fma2(mul2(ovA[2 * i], rs32), n.x, xn[2 * i]);
            r.y = fma2(mul2(ovA[2 * i + 1], rs32), n.y, xn[2 * i + 1]);
            xo[i] = r;
        }
        rs3 = rsqrtf(sumsq16(ovB) * 0.03125f + 1e-6f);
        rs32 = pack2(rs3, rs3);
        ld_row16(xn, sx + (tid + 128) * 36);
        xo = (ulonglong2*)(sx + (tid + 128) * 36);
#pragma unroll
        for (int i = 0; i < 8; i++) {
            ulonglong2 n = nw[i];
            ulonglong2 r;
            r.x = fma2(mul2(ovB[2 * i], rs32), n.x, xn[2 * i]);
            r.y = fma2(mul2(ovB[2 * i + 1], rs32), n.y, xn[2 * i + 1]);
            xo[i] = r;
        }
    }
    __syncthreads();
    for (int i = tid; i < 2048; i += 128)
        ((float4*)(g_tokens + base))[i] = *(const float4*)(sx + (i >> 3) * 36 + (i & 7) * 4);
}

// ---------------------------------------------------------------------------
// Final: rmsnorm + extract 3 CLS tokens of last timestep.
// ---------------------------------------------------------------------------
__global__ void final_kernel(const float* __restrict__ fnorm, float* __restrict__ out) {
    int b = blockIdx.x / 3, k = blockIdx.x % 3, lane = threadIdx.x;
    float x = g_tokens[(((long)b * 128 + 127) * 67 + 64 + k) * 32 + lane];
    float ms = warp_sum(x * x) * (1.f / 32.f);
    out[(k * 16 + b) * 32 + lane] = x * rsqrtf(ms + 1e-6f) * fnorm[lane];
}

// ---------------------------------------------------------------------------
// Launch
// ---------------------------------------------------------------------------
extern "C" void kernel_launch(void* const* d_in, const int* in_sizes, int n_in,
                              void* d_out, int out_size) {
    const float* obs    = (const float*)d_in[0];
    const float* Wval   = (const float*)d_in[1];
    const float* bval   = (const float*)d_in[2];
    const float* innorm = (const float*)d_in[3];
    const float* dimemb = (const float*)d_in[4];
    const float* cls    = (const float*)d_in[5];
    const float* fnorm  = (const float*)d_in[6];
    const float* sWq   = (const float*)d_in[7];
    const float* sWk   = (const float*)d_in[8];
    const float* sWv   = (const float*)d_in[9];
    const float* sWo   = (const float*)d_in[10];
    const float* sWg   = (const float*)d_in[11];
    const float* sWu   = (const float*)d_in[12];
    const float* sWout = (const float*)d_in[13];
    const float* sN4   = (const float*)d_in[14];
    const float* sQKN  = (const float*)d_in[15];
    const float* tWq   = (const float*)d_in[16];
    const float* tWk   = (const float*)d_in[17];
    const float* tWv   = (const float*)d_in[18];
    const float* tWo   = (const float*)d_in[19];
    const float* tWg   = (const float*)d_in[20];
    const float* tWu   = (const float*)d_in[21];
    const float* tWout = (const float*)d_in[22];
    const float* tN4   = (const float*)d_in[23];
    const float* tQKN  = (const float*)d_in[24];

    // attn smem: NSEQ*SEQSTR + 4096 + 80 floats
    const int SEQSTR_S = 2 * 67 * 36;          // 4824 (not mult of 32 -> no pad)
    const int SEQSTR_T = 2 * 128 * 36 + 8;     // 9224
    const int SZ_AS = (3 * SEQSTR_S + 4096 + 80) * 4;   // 74592
    const int SZ_AT = (2 * SEQSTR_T + 4096 + 80) * 4;   // 90496
    const int SZ_F  = (9216 + 3 * 2048 + 64) * 4;       // 61696

    cudaFuncSetAttribute(attn_half<67, 3, 3, false>, cudaFuncAttributeMaxDynamicSharedMemorySize, SZ_AS);
    cudaFuncSetAttribute(attn_half<128, 2, 2, true>, cudaFuncAttributeMaxDynamicSharedMemorySize, SZ_AT);
    cudaFuncSetAttribute(ffn_half, cudaFuncAttributeMaxDynamicSharedMemorySize, SZ_F);

    embed_kernel<<<2048, 256>>>(obs, Wval, bval, innorm, dimemb, cls);

    const int GRID_AS = (2048 + 2) / 3;   // 683
    const int GRID_AT = 1072 / 2;         // 536
    const int GRID_F  = 536;              // 137216 / 256

    for (int layer = 0; layer < 3; layer++) {
        attn_half<67, 3, 3, false><<<GRID_AS, 128, SZ_AS>>>(
            sWq + layer * 1024, sWk + layer * 1024, sWv + layer * 1024, sWo + layer * 1024,
            sN4 + layer * 128, sQKN + layer * 16, 2048);
        ffn_half<<<GRID_F, 128, SZ_F>>>(
            sWg + layer * 2048, sWu + layer * 2048, sWout + layer * 2048,
            sN4 + layer * 128 + 64);
        if (layer < 2) {
            attn_half<128, 2, 2, true><<<GRID_AT, 128, SZ_AT>>>(
                tWq + layer * 1024, tWk + layer * 1024, tWv + layer * 1024, tWo + layer * 1024,
                tN4 + layer * 128, tQKN + layer * 16, 1072);
            ffn_half<<<GRID_F, 128, SZ_F>>>(
                tWg + layer * 2048, tWu + layer * 2048, tWout + layer * 2048,
                tN4 + layer * 128 + 64);
        }
    }

    final_kernel<<<48, 32>>>(fnorm, (float*)d_out);
}

// round 12
// speedup vs baseline: 1.2203x; 1.2203x over previous
#include <cuda_runtime.h>
#include <math.h>

#define FULL 0xffffffffu
typedef unsigned long long u64;

// Scratch token buffer: (B=16, T=128, slots=67, EMBED=32) fp32
__device__ float g_tokens[16 * 128 * 67 * 32];

__device__ __forceinline__ float warp_sum(float v) {
    v += __shfl_xor_sync(FULL, v, 16);
    v += __shfl_xor_sync(FULL, v, 8);
    v += __shfl_xor_sync(FULL, v, 4);
    v += __shfl_xor_sync(FULL, v, 2);
    v += __shfl_xor_sync(FULL, v, 1);
    return v;
}

// ---- packed f32x2 helpers ----
__device__ __forceinline__ u64 fma2(u64 a, u64 b, u64 c) {
    u64 d; asm("fma.rn.f32x2 %0, %1, %2, %3;" : "=l"(d) : "l"(a), "l"(b), "l"(c)); return d;
}
__device__ __forceinline__ u64 mul2(u64 a, u64 b) {
    u64 d; asm("mul.rn.f32x2 %0, %1, %2;" : "=l"(d) : "l"(a), "l"(b)); return d;
}
__device__ __forceinline__ u64 add2(u64 a, u64 b) {
    u64 d; asm("add.rn.f32x2 %0, %1, %2;" : "=l"(d) : "l"(a), "l"(b)); return d;
}
__device__ __forceinline__ u64 pack2(float lo, float hi) {
    u64 d; asm("mov.b64 %0, {%1, %2};" : "=l"(d) : "f"(lo), "f"(hi)); return d;
}
__device__ __forceinline__ float hsum2(u64 v) {
    float lo, hi; asm("mov.b64 {%0, %1}, %2;" : "=f"(lo), "=f"(hi) : "l"(v)); return lo + hi;
}
__device__ __forceinline__ void unpk(u64 v, float& a, float& b) {
    asm("mov.b64 {%0, %1}, %2;" : "=f"(a), "=f"(b) : "l"(v));
}
// base-2 exp, scores pre-scaled by log2(e)
__device__ __forceinline__ float ex2f(float x) {
    float y; asm("ex2.approx.f32 %0, %1;" : "=f"(y) : "f"(x)); return y;
}

__device__ __forceinline__ void ld_row16(u64* r, const float* p) {
    const ulonglong2* q = (const ulonglong2*)p;
#pragma unroll
    for (int i = 0; i < 8; i++) { ulonglong2 t = q[i]; r[2 * i] = t.x; r[2 * i + 1] = t.y; }
}

// one weight row read, TWO dots (token pair)
__device__ __forceinline__ float2 dot32x2(const float* wrow, const u64* a, const u64* b) {
    const ulonglong2* w = (const ulonglong2*)wrow;
    ulonglong2 t0 = w[0], t1 = w[1];
    u64 a0 = mul2(a[0], t0.x), b0 = mul2(b[0], t0.x);
    a0 = fma2(a[1], t0.y, a0); b0 = fma2(b[1], t0.y, b0);
    u64 a1 = mul2(a[2], t1.x), b1 = mul2(b[2], t1.x);
    a1 = fma2(a[3], t1.y, a1); b1 = fma2(b[3], t1.y, b1);
#pragma unroll
    for (int i = 2; i < 8; i += 2) {
        ulonglong2 u0 = w[i], u1 = w[i + 1];
        a0 = fma2(a[2 * i], u0.x, a0);     b0 = fma2(b[2 * i], u0.x, b0);
        a0 = fma2(a[2 * i + 1], u0.y, a0); b0 = fma2(b[2 * i + 1], u0.y, b0);
        a1 = fma2(a[2 * i + 2], u1.x, a1); b1 = fma2(b[2 * i + 2], u1.x, b1);
        a1 = fma2(a[2 * i + 3], u1.y, a1); b1 = fma2(b[2 * i + 3], u1.y, b1);
    }
    return make_float2(hsum2(add2(a0, a1)), hsum2(add2(b0, b1)));
}

__device__ __forceinline__ float sumsq16(const u64* v) {
    u64 a0 = mul2(v[0], v[0]);
    u64 a1 = mul2(v[1], v[1]);
#pragma unroll
    for (int i = 2; i < 16; i += 2) {
        a0 = fma2(v[i], v[i], a0);
        a1 = fma2(v[i + 1], v[i + 1], a1);
    }
    return hsum2(add2(a0, a1));
}

// ---------------------------------------------------------------------------
// Kernel 0: tokenize + input rmsnorm. grid = B*T (2048), block = 256.
// ---------------------------------------------------------------------------
__global__ void embed_kernel(const float* __restrict__ obs,
                             const float* __restrict__ Wval,
                             const float* __restrict__ bval,
                             const float* __restrict__ innorm,
                             const float* __restrict__ dimemb,
                             const float* __restrict__ cls) {
    int bt = blockIdx.x;
    int tid = threadIdx.x;
    int wid = tid >> 5, lane = tid & 31;
    for (int s = wid; s < 67; s += 8) {
        float val;
        if (s < 64)
            val = fmaf(obs[bt * 64 + s], Wval[lane], bval[lane]) + dimemb[s * 32 + lane];
        else
            val = cls[(s - 64) * 32 + lane];
        float ms = warp_sum(val * val) * (1.f / 32.f);
        g_tokens[(bt * 67 + s) * 32 + lane] = val * rsqrtf(ms + 1e-6f) * innorm[lane];
    }
}

// ---------------------------------------------------------------------------
// Monolithic fused block with TRANSPOSED-K attention:
// K stored as K^T[dim][key] (keys contiguous, padded to mult of 4 with zero
// columns). Scores accumulate natively packed over key pairs via fma2 with
// duplicated q — no per-score horizontal sum. Zero pad keys give p=1.0,
// subtracted exactly from the softmax denominator.
// Two tokens per lane; two head-split passes. Base-2 softmax.
// ---------------------------------------------------------------------------
template <int S, int NSEQ, bool TEMPORAL>
__global__ void __launch_bounds__(32 * ((((S + 1) / 2) * NSEQ + 31) / 32))
attn_tpl(const float* __restrict__ Wq, const float* __restrict__ Wk,
         const float* __restrict__ Wv, const float* __restrict__ Wo,
         const float* __restrict__ Wg, const float* __restrict__ Wu,
         const float* __restrict__ Wout, const float* __restrict__ norm4,
         const float* __restrict__ qkn, int nseq_total) {
    constexpr int HS = (S + 1) / 2;
    constexpr int BLK = 32 * ((HS * NSEQ + 31) / 32);
    constexpr int SP4 = ((S + 3) / 4) * 4;       // keys padded to mult of 4
    constexpr int PADK = SP4 - S;
    constexpr int ROW = 36;                      // V row stride
    constexpr int KTSZ = 32 * SP4;               // K^T area per seq
    constexpr int SEQSTR = KTSZ + SP4 * ROW;
    constexpr int DATSZ = NSEQ * SEQSTR;

    extern __shared__ float sm[];
    float* skv   = sm;                 // DATSZ
    float* swq   = skv + DATSZ;        // 1024
    float* swk   = swq + 1024;
    float* swv   = swk + 1024;
    float* swo   = swv + 1024;
    float* swg   = swo + 1024;         // 2048
    float* swu   = swg + 2048;         // 2048
    float* swout = swu + 2048;         // 2048 transposed [f][d]
    float* snorm = swout + 2048;       // 128
    float* sqkn  = snorm + 128;        // 16

    const int tid = threadIdx.x;
    int gseq0 = blockIdx.x * NSEQ;

    // ---- stage weights ----
    for (int i = tid; i < 256; i += BLK) {
        ((float4*)swq)[i] = ((const float4*)Wq)[i];
        ((float4*)swk)[i] = ((const float4*)Wk)[i];
        ((float4*)swv)[i] = ((const float4*)Wv)[i];
        ((float4*)swo)[i] = ((const float4*)Wo)[i];
    }
    for (int i = tid; i < 512; i += BLK) {
        ((float4*)swg)[i] = ((const float4*)Wg)[i];
        ((float4*)swu)[i] = ((const float4*)Wu)[i];
    }
    for (int i = tid; i < 2048; i += BLK) {   // transpose Wout -> [f][d]
        int f = i >> 5, d = i & 31;
        swout[i] = Wout[d * 64 + f];
    }
    if (tid < 128) snorm[tid] = norm4[tid];
    if (tid < 16) sqkn[tid] = qkn[tid];

    // ---- zero pad keys: K^T columns S..SP4-1 (32 dims) + V rows S..SP4-1 --
    if (PADK > 0) {
        constexpr int PER = (32 + ROW) * PADK;
        for (int i = tid; i < NSEQ * PER; i += BLK) {
            int sq = i / PER;
            int r = i - sq * PER;
            float* sb = skv + sq * SEQSTR;
            if (r < 32 * PADK) {
                int d = r / PADK, pc = r - d * PADK;
                sb[d * SP4 + S + pc] = 0.f;
            } else {
                int rr = r - 32 * PADK;
                sb[KTSZ + (S + rr / ROW) * ROW + rr % ROW] = 0.f;
            }
        }
    }

    // ---- token-pair assignment ----
    int seq = tid / HS;
    int l = tid - seq * HS;
    bool seqok = (seq < NSEQ) && (gseq0 + seq < nseq_total);
    int seqc = seqok ? seq : 0;
    bool vA = seqok;
    bool vB = seqok && (l + HS < S);
    int tokA = l;
    int tokB = vB ? (l + HS) : (S - 1);

    float* kT = skv + seqc * SEQSTR;
    float* vb = kT + KTSZ;

    float *gxA, *gxB;
    {
        int gs = gseq0 + seqc;
        if (TEMPORAL) {
            int b = gs / 67, sl = gs - b * 67;
            gxA = g_tokens + ((long)(b * 128 + tokA) * 67 + sl) * 32;
            gxB = g_tokens + ((long)(b * 128 + tokB) * 67 + sl) * 32;
        } else {
            gxA = g_tokens + ((long)gs * 67 + tokA) * 32;
            gxB = g_tokens + ((long)gs * 67 + tokB) * 32;
        }
    }

    __syncthreads();

    u64 qA[16], qB[16];

    // ================= Phase B: norm + QKV (+qk-norm, rope) ================
    if (vA) {
        float qknQ[8], qknK[8];
#pragma unroll
        for (int e = 0; e < 8; e++) {
            qknQ[e] = sqkn[e] * (0.35355339059327373f * 1.4426950408889634f);
            qknK[e] = sqkn[8 + e];
        }
        float csA[4], snA[4], csB[4], snB[4];
        if (TEMPORAL) {
            const float th[4] = {1.f, 0.1f, 0.01f, 0.001f};
#pragma unroll
            for (int j = 0; j < 4; j++) {
                __sincosf((float)tokA * th[j], &snA[j], &csA[j]);
                __sincosf((float)tokB * th[j], &snB[j], &csB[j]);
            }
        }

        u64 hA[16], hB[16];
        {
            u64 x2[16];
            ld_row16(x2, gxA);
            float rs = rsqrtf(sumsq16(x2) * 0.03125f + 1e-6f);
            u64 rs2 = pack2(rs, rs);
            const ulonglong2* nw = (const ulonglong2*)snorm;
#pragma unroll
            for (int i = 0; i < 8; i++) {
                ulonglong2 n = nw[i];
                hA[2 * i] = mul2(mul2(x2[2 * i], rs2), n.x);
                hA[2 * i + 1] = mul2(mul2(x2[2 * i + 1], rs2), n.y);
            }
            ld_row16(x2, gxB);
            rs = rsqrtf(sumsq16(x2) * 0.03125f + 1e-6f);
            rs2 = pack2(rs, rs);
#pragma unroll
            for (int i = 0; i < 8; i++) {
                ulonglong2 n = nw[i];
                hB[2 * i] = mul2(mul2(x2[2 * i], rs2), n.x);
                hB[2 * i + 1] = mul2(mul2(x2[2 * i + 1], rs2), n.y);
            }
        }

        // ---- K heads: store into K^T (keys contiguous) ----
#pragma unroll 1
        for (int hh = 0; hh < 4; hh++) {
            float aA[8], aB[8];
#pragma unroll
            for (int e = 0; e < 8; e++) {
                float2 d = dot32x2(swk + (hh * 8 + e) * 32, hA, hB);
                aA[e] = d.x; aB[e] = d.y;
            }
            float msA = 0, msB = 0;
#pragma unroll
            for (int e = 0; e < 8; e++) { msA = fmaf(aA[e], aA[e], msA); msB = fmaf(aB[e], aB[e], msB); }
            float scA = rsqrtf(msA * 0.125f + 1e-6f);
            float scB = rsqrtf(msB * 0.125f + 1e-6f);
#pragma unroll
            for (int e = 0; e < 8; e++) { aA[e] *= scA * qknK[e]; aB[e] *= scB * qknK[e]; }
            if (TEMPORAL) {
#pragma unroll
                for (int e = 0; e < 4; e++) {
                    float t0 = aA[e], t1 = aA[e + 4];
                    aA[e] = t0 * csA[e] - t1 * snA[e];
                    aA[e + 4] = fmaf(t0, snA[e], t1 * csA[e]);
                    t0 = aB[e]; t1 = aB[e + 4];
                    aB[e] = t0 * csB[e] - t1 * snB[e];
                    aB[e + 4] = fmaf(t0, snB[e], t1 * csB[e]);
                }
            }
#pragma unroll
            for (int e = 0; e < 8; e++) {
                kT[(hh * 8 + e) * SP4 + tokA] = aA[e];
                if (vB) kT[(hh * 8 + e) * SP4 + tokB] = aB[e];
            }
        }

        // ---- V heads (row-major) ----
#pragma unroll 1
        for (int hh = 0; hh < 4; hh++) {
            float aA[8], aB[8];
#pragma unroll
            for (int e = 0; e < 8; e++) {
                float2 d = dot32x2(swv + (hh * 8 + e) * 32, hA, hB);
                aA[e] = d.x; aB[e] = d.y;
            }
            float* dA = vb + tokA * ROW + hh * 8;
            *(float4*)dA = make_float4(aA[0], aA[1], aA[2], aA[3]);
            *(float4*)(dA + 4) = make_float4(aA[4], aA[5], aA[6], aA[7]);
            if (vB) {
                float* dB = vb + tokB * ROW + hh * 8;
                *(float4*)dB = make_float4(aB[0], aB[1], aB[2], aB[3]);
                *(float4*)(dB + 4) = make_float4(aB[4], aB[5], aB[6], aB[7]);
            }
        }

        // ---- Q heads ----
#pragma unroll
        for (int hh = 0; hh < 4; hh++) {
            float aA[8], aB[8];
#pragma unroll
            for (int e = 0; e < 8; e++) {
                float2 d = dot32x2(swq + (hh * 8 + e) * 32, hA, hB);
                aA[e] = d.x; aB[e] = d.y;
            }
            float msA = 0, msB = 0;
#pragma unroll
            for (int e = 0; e < 8; e++) { msA = fmaf(aA[e], aA[e], msA); msB = fmaf(aB[e], aB[e], msB); }
            float scA = rsqrtf(msA * 0.125f + 1e-6f);
            float scB = rsqrtf(msB * 0.125f + 1e-6f);
#pragma unroll
            for (int e = 0; e < 8; e++) { aA[e] *= scA * qknQ[e]; aB[e] *= scB * qknQ[e]; }
            if (TEMPORAL) {
#pragma unroll
                for (int e = 0; e < 4; e++) {
                    float t0 = aA[e], t1 = aA[e + 4];
                    aA[e] = t0 * csA[e] - t1 * snA[e];
                    aA[e + 4] = fmaf(t0, snA[e], t1 * csA[e]);
                    t0 = aB[e]; t1 = aB[e + 4];
                    aB[e] = t0 * csB[e] - t1 * snB[e];
                    aB[e + 4] = fmaf(t0, snB[e], t1 * csB[e]);
                }
            }
#pragma unroll
            for (int j = 0; j < 4; j++) {
                qA[4 * hh + j] = pack2(aA[2 * j], aA[2 * j + 1]);
                qB[4 * hh + j] = pack2(aB[2 * j], aB[2 * j + 1]);
            }
        }
    }
    __syncthreads();

    // ====== Phase C: packed-score attention, two head-split passes =========
    u64 oA[16], oB[16];
    if (vA) {
#pragma unroll
        for (int pass = 0; pass < 2; pass++) {
            // duplicate-packed q for this pass's 16 dims
            u64 qdA[16], qdB[16];
#pragma unroll
            for (int i = 0; i < 8; i++) {
                float lo, hi;
                unpk(qA[8 * pass + i], lo, hi);
                qdA[2 * i] = pack2(lo, lo); qdA[2 * i + 1] = pack2(hi, hi);
                unpk(qB[8 * pass + i], lo, hi);
                qdB[2 * i] = pack2(lo, lo); qdB[2 * i + 1] = pack2(hi, hi);
            }
            u64 aA[8], aB[8];
#pragma unroll
            for (int i = 0; i < 8; i++) { aA[i] = 0ULL; aB[i] = 0ULL; }
            float l0A = 0.f, l1A = 0.f, l0B = 0.f, l1B = 0.f;
            const float* kTp = kT + (16 * pass) * SP4;
            const float* vp = vb + 16 * pass;

#pragma unroll 1
            for (int jb = 0; jb < SP4; jb += 4) {
                // scores for keys jb..jb+3, packed per key pair
                u64 sA0a = 0, sA0b = 0, sA1a = 0, sA1b = 0;
                u64 sB0a = 0, sB0b = 0, sB1a = 0, sB1b = 0;
#pragma unroll
                for (int d = 0; d < 8; d++) {
                    ulonglong2 t0 = *(const ulonglong2*)(kTp + d * SP4 + jb);
                    ulonglong2 t1 = *(const ulonglong2*)(kTp + (d + 8) * SP4 + jb);
                    sA0a = fma2(qdA[d], t0.x, sA0a); sA0b = fma2(qdA[d], t0.y, sA0b);
                    sB0a = fma2(qdB[d], t0.x, sB0a); sB0b = fma2(qdB[d], t0.y, sB0b);
                    sA1a = fma2(qdA[8 + d], t1.x, sA1a); sA1b = fma2(qdA[8 + d], t1.y, sA1b);
                    sB1a = fma2(qdB[8 + d], t1.x, sB1a); sB1b = fma2(qdB[8 + d], t1.y, sB1b);
                }
                float pA0[4], pA1[4], pB0[4], pB1[4];
                unpk(sA0a, pA0[0], pA0[1]); unpk(sA0b, pA0[2], pA0[3]);
                unpk(sA1a, pA1[0], pA1[1]); unpk(sA1b, pA1[2], pA1[3]);
                unpk(sB0a, pB0[0], pB0[1]); unpk(sB0b, pB0[2], pB0[3]);
                unpk(sB1a, pB1[0], pB1[1]); unpk(sB1b, pB1[2], pB1[3]);
#pragma unroll
                for (int jj = 0; jj < 4; jj++) {
                    pA0[jj] = ex2f(pA0[jj]); l0A += pA0[jj];
                    pA1[jj] = ex2f(pA1[jj]); l1A += pA1[jj];
                    pB0[jj] = ex2f(pB0[jj]); l0B += pB0[jj];
                    pB1[jj] = ex2f(pB1[jj]); l1B += pB1[jj];
                }
#pragma unroll
                for (int jj = 0; jj < 4; jj++) {
                    const ulonglong2* vr = (const ulonglong2*)(vp + (jb + jj) * ROW);
                    ulonglong2 v0 = vr[0], v1 = vr[1], v2 = vr[2], v3 = vr[3];
                    u64 pp;
                    pp = pack2(pA0[jj], pA0[jj]);
                    aA[0] = fma2(pp, v0.x, aA[0]); aA[1] = fma2(pp, v0.y, aA[1]);
                    aA[2] = fma2(pp, v1.x, aA[2]); aA[3] = fma2(pp, v1.y, aA[3]);
                    pp = pack2(pA1[jj], pA1[jj]);
                    aA[4] = fma2(pp, v2.x, aA[4]); aA[5] = fma2(pp, v2.y, aA[5]);
                    aA[6] = fma2(pp, v3.x, aA[6]); aA[7] = fma2(pp, v3.y, aA[7]);
                    pp = pack2(pB0[jj], pB0[jj]);
                    aB[0] = fma2(pp, v0.x, aB[0]); aB[1] = fma2(pp, v0.y, aB[1]);
                    aB[2] = fma2(pp, v1.x, aB[2]); aB[3] = fma2(pp, v1.y, aB[3]);
                    pp = pack2(pB1[jj], pB1[jj]);
                    aB[4] = fma2(pp, v2.x, aB[4]); aB[5] = fma2(pp, v2.y, aB[5]);
                    aB[6] = fma2(pp, v3.x, aB[6]); aB[7] = fma2(pp, v3.y, aB[7]);
                }
            }
            // pad keys contributed exactly 1.0 each
            l0A -= (float)PADK; l1A -= (float)PADK;
            l0B -= (float)PADK; l1B -= (float)PADK;

            float i0A = __fdividef(1.f, l0A), i1A = __fdividef(1.f, l1A);
            float i0B = __fdividef(1.f, l0B), i1B = __fdividef(1.f, l1B);
            u64 z;
            z = pack2(i0A, i0A);
#pragma unroll
            for (int i = 0; i < 4; i++) oA[8 * pass + i] = mul2(aA[i], z);
            z = pack2(i1A, i1A);
#pragma unroll
            for (int i = 4; i < 8; i++) oA[8 * pass + i] = mul2(aA[i], z);
            z = pack2(i0B, i0B);
#pragma unroll
            for (int i = 0; i < 4; i++) oB[8 * pass + i] = mul2(aB[i], z);
            z = pack2(i1B, i1B);
#pragma unroll
            for (int i = 4; i < 8; i++) oB[8 * pass + i] = mul2(aB[i], z);
        }
    }
    __syncthreads();   // all warps done reading K^T/V -> V area reusable

    // ================= Phase D: Wo + residual + FFN + residual =============
    if (vA) {
        float owA[32], owB[32];
        float ssA = 0.f, ssB = 0.f;
#pragma unroll
        for (int d = 0; d < 32; d++) {
            float2 r = dot32x2(swo + d * 32, oA, oB);
            owA[d] = r.x; owB[d] = r.y;
            ssA = fmaf(r.x, r.x, ssA);
            ssB = fmaf(r.y, r.y, ssB);
        }
        float rAs = rsqrtf(ssA * 0.03125f + 1e-6f);
        float rBs = rsqrtf(ssB * 0.03125f + 1e-6f);
        u64 rsA = pack2(rAs, rAs);
        u64 rsB = pack2(rBs, rBs);

        u64 h2A[16], h2B[16];
        {
            u64 x2[16], xn[16];
            const ulonglong2* nw1 = (const ulonglong2*)(snorm + 32);
            const ulonglong2* nw2 = (const ulonglong2*)(snorm + 64);
            ld_row16(x2, gxA);
#pragma unroll
            for (int i = 0; i < 8; i++) {
                ulonglong2 n = nw1[i];
                xn[2 * i] = fma2(mul2(pack2(owA[4 * i], owA[4 * i + 1]), rsA), n.x, x2[2 * i]);
                xn[2 * i + 1] = fma2(mul2(pack2(owA[4 * i + 2], owA[4 * i + 3]), rsA), n.y, x2[2 * i + 1]);
            }
            {
                ulonglong2* xo = (ulonglong2*)(vb + tokA * ROW);
#pragma unroll
                for (int i = 0; i < 8; i++) { ulonglong2 t; t.x = xn[2 * i]; t.y = xn[2 * i + 1]; xo[i] = t; }
            }
            float rsa = rsqrtf(sumsq16(xn) * 0.03125f + 1e-6f);
            u64 rsa2 = pack2(rsa, rsa);
#pragma unroll
            for (int i = 0; i < 8; i++) {
                ulonglong2 n = nw2[i];
                h2A[2 * i] = mul2(mul2(xn[2 * i], rsa2), n.x);
                h2A[2 * i + 1] = mul2(mul2(xn[2 * i + 1], rsa2), n.y);
            }
            // token B
            ld_row16(x2, gxB);
#pragma unroll
            for (int i = 0; i < 8; i++) {
                ulonglong2 n = nw1[i];
                xn[2 * i] = fma2(mul2(pack2(owB[4 * i], owB[4 * i + 1]), rsB), n.x, x2[2 * i]);
                xn[2 * i + 1] = fma2(mul2(pack2(owB[4 * i + 2], owB[4 * i + 3]), rsB), n.y, x2[2 * i + 1]);
            }
            if (vB) {
                ulonglong2* xo = (ulonglong2*)(vb + tokB * ROW);
#pragma unroll
                for (int i = 0; i < 8; i++) { ulonglong2 t; t.x = xn[2 * i]; t.y = xn[2 * i + 1]; xo[i] = t; }
            }
            float rsb = rsqrtf(sumsq16(xn) * 0.03125f + 1e-6f);
            u64 rsb2 = pack2(rsb, rsb);
#pragma unroll
            for (int i = 0; i < 8; i++) {
                ulonglong2 n = nw2[i];
                h2B[2 * i] = mul2(mul2(xn[2 * i], rsb2), n.x);
                h2B[2 * i + 1] = mul2(mul2(xn[2 * i + 1], rsb2), n.y);
            }
        }

        // ---- FFN ----
        u64 ovA[16], ovB[16];
#pragma unroll
        for (int i = 0; i < 16; i++) { ovA[i] = 0ULL; ovB[i] = 0ULL; }

#pragma unroll 1
        for (int fg = 0; fg < 16; fg++) {
#pragma unroll
            for (int e = 0; e < 4; e++) {
                int f = fg * 4 + e;
                float2 g2 = dot32x2(swg + f * 32, h2A, h2B);
                float2 u2 = dot32x2(swu + f * 32, h2A, h2B);
                float fvA = __fdividef(g2.x, 1.f + __expf(-g2.x)) * u2.x;
                float fvB = __fdividef(g2.y, 1.f + __expf(-g2.y)) * u2.y;
                u64 fA = pack2(fvA, fvA), fB = pack2(fvB, fvB);
                const ulonglong2* wr = (const ulonglong2*)(swout + f * 32);
#pragma unroll
                for (int i = 0; i < 8; i++) {
                    ulonglong2 t = wr[i];
                    ovA[2 * i] = fma2(fA, t.x, ovA[2 * i]);
                    ovA[2 * i + 1] = fma2(fA, t.y, ovA[2 * i + 1]);
                    ovB[2 * i] = fma2(fB, t.x, ovB[2 * i]);
                    ovB[2 * i + 1] = fma2(fB, t.y, ovB[2 * i + 1]);
                }
            }
        }

        // ---- out = xn + rmsnorm(ov), reload xn from V-area, store gmem ----
        {
            const ulonglong2* nw = (const ulonglong2*)(snorm + 96);
            float rs3 = rsqrtf(sumsq16(ovA) * 0.03125f + 1e-6f);
            u64 rs32 = pack2(rs3, rs3);
            u64 xn[16];
            ld_row16(xn, vb + tokA * ROW);
            ulonglong2* go = (ulonglong2*)gxA;
#pragma unroll
            for (int i = 0; i < 8; i++) {
                ulonglong2 n = nw[i];
                ulonglong2 r;
                r.x = fma2(mul2(ovA[2 * i], rs32), n.x, xn[2 * i]);
                r.y = fma2(mul2(ovA[2 * i + 1], rs32), n.y, xn[2 * i + 1]);
                go[i] = r;
            }
            if (vB) {
                rs3 = rsqrtf(sumsq16(ovB) * 0.03125f + 1e-6f);
                rs32 = pack2(rs3, rs3);
                ld_row16(xn, vb + tokB * ROW);
                go = (ulonglong2*)gxB;
#pragma unroll
                for (int i = 0; i < 8; i++) {
                    ulonglong2 n = nw[i];
                    ulonglong2 r;
                    r.x = fma2(mul2(ovB[2 * i], rs32), n.x, xn[2 * i]);
                    r.y = fma2(mul2(ovB[2 * i + 1], rs32), n.y, xn[2 * i + 1]);
                    go[i] = r;
                }
            }
        }
    }
}

// ---------------------------------------------------------------------------
// Final: rmsnorm + extract 3 CLS tokens of last timestep.
// ---------------------------------------------------------------------------
__global__ void final_kernel(const float* __restrict__ fnorm, float* __restrict__ out) {
    int b = blockIdx.x / 3, k = blockIdx.x % 3, lane = threadIdx.x;
    float x = g_tokens[(((long)b * 128 + 127) * 67 + 64 + k) * 32 + lane];
    float ms = warp_sum(x * x) * (1.f / 32.f);
    out[(k * 16 + b) * 32 + lane] = x * rsqrtf(ms + 1e-6f) * fnorm[lane];
}

// ---------------------------------------------------------------------------
// Launch
// ---------------------------------------------------------------------------
extern "C" void kernel_launch(void* const* d_in, const int* in_sizes, int n_in,
                              void* d_out, int out_size) {
    const float* obs    = (const float*)d_in[0];
    const float* Wval   = (const float*)d_in[1];
    const float* bval   = (const float*)d_in[2];
    const float* innorm = (const float*)d_in[3];
    const float* dimemb = (const float*)d_in[4];
    const float* cls    = (const float*)d_in[5];
    const float* fnorm  = (const float*)d_in[6];
    const float* sWq   = (const float*)d_in[7];
    const float* sWk   = (const float*)d_in[8];
    const float* sWv   = (const float*)d_in[9];
    const float* sWo   = (const float*)d_in[10];
    const float* sWg   = (const float*)d_in[11];
    const float* sWu   = (const float*)d_in[12];
    const float* sWout = (const float*)d_in[13];
    const float* sN4   = (const float*)d_in[14];
    const float* sQKN  = (const float*)d_in[15];
    const float* tWq   = (const float*)d_in[16];
    const float* tWk   = (const float*)d_in[17];
    const float* tWv   = (const float*)d_in[18];
    const float* tWo   = (const float*)d_in[19];
    const float* tWg   = (const float*)d_in[20];
    const float* tWu   = (const float*)d_in[21];
    const float* tWout = (const float*)d_in[22];
    const float* tN4   = (const float*)d_in[23];
    const float* tQKN  = (const float*)d_in[24];

    // smem floats: NSEQ*(32*SP4 + SP4*36) + 10240 + 144
    const int SZ_S = (3 * (32 * 68 + 68 * 36) + 10240 + 144) * 4;     // 97072
    const int SZ_T = (4 * (32 * 128 + 128 * 36) + 10240 + 144) * 4;   // 180800

    cudaFuncSetAttribute(attn_tpl<67, 3, false>, cudaFuncAttributeMaxDynamicSharedMemorySize, SZ_S);
    cudaFuncSetAttribute(attn_tpl<128, 4, true>, cudaFuncAttributeMaxDynamicSharedMemorySize, SZ_T);

    embed_kernel<<<2048, 256>>>(obs, Wval, bval, innorm, dimemb, cls);

    const int GRID_S = (2048 + 2) / 3;   // 683
    const int GRID_T = 1072 / 4;         // 268

    for (int layer = 0; layer < 3; layer++) {
        attn_tpl<67, 3, false><<<GRID_S, 128, SZ_S>>>(
            sWq + layer * 1024, sWk + layer * 1024, sWv + layer * 1024, sWo + layer * 1024,
            sWg + layer * 2048, sWu + layer * 2048, sWout + layer * 2048,
            sN4 + layer * 128, sQKN + layer * 16, 2048);
        if (layer < 2) {
            attn_tpl<128, 4, true><<<GRID_T, 256, SZ_T>>>(
                tWq + layer * 1024, tWk + layer * 1024, tWv + layer * 1024, tWo + layer * 1024,
                tWg + layer * 2048, tWu + layer * 2048, tWout + layer * 2048,
                tN4 + layer * 128, tQKN + layer * 16, 1072);
        }
    }

    final_kernel<<<48, 32>>>(fnorm, (float*)d_out);
}